// round 1
// baseline (speedup 1.0000x reference)
#include <cuda_runtime.h>
#include <math.h>

#define B_TOT   65536
#define Z_DIM   128
#define T_STEPS 40
#define P_DIM   50
#define H_DIM   100
#define G4      400      // 4*H
#define DT      0.1f

#define MCH     64       // batch elements per CTA in rollout
#define NTHR    320      // 16 m-groups (4 elems) x 20 u-groups (5 units)
#define HS      68       // padded stride for h_sh rows (bank-conflict relief, 16B-aligned)

// scratch: xk[b][j] = proj(b) @ lstm_k[:50] + lstm_b   (104.8 MB, static device alloc)
__device__ float g_xk[(size_t)B_TOT * G4];

// ---------------------------------------------------------------------------
// Kernel A: proj = relu(relu(z@W1+b1)@W2+b2);  xk = proj @ lstm_k[0:50] + lstm_b
// One warp per element. Weights read through L1/L2 (tiny, hot).
// ---------------------------------------------------------------------------
__global__ void __launch_bounds__(256) proj_xk_kernel(
    const float* __restrict__ z,       // B x 128
    const float* __restrict__ W1,      // 128 x 50
    const float* __restrict__ b1,      // 50
    const float* __restrict__ W2,      // 50 x 50
    const float* __restrict__ b2,      // 50
    const float* __restrict__ lstm_k,  // 52 x 400
    const float* __restrict__ lstm_b)  // 400
{
    const int warp  = threadIdx.x >> 5;
    const int lane  = threadIdx.x & 31;
    const int wpc   = blockDim.x >> 5;

    for (int b = blockIdx.x * wpc + warp; b < B_TOT; b += gridDim.x * wpc) {
        // z into 4 regs per lane
        float zr[4];
        #pragma unroll
        for (int q = 0; q < 4; q++) zr[q] = z[(size_t)b * Z_DIM + q * 32 + lane];

        // layer 1: columns j0=lane, j1=32+lane (lane<18)
        float a0 = b1[lane];
        float a1 = (lane < 18) ? b1[32 + lane] : 0.f;
        for (int i = 0; i < Z_DIM; i++) {
            float zi = __shfl_sync(0xffffffffu, zr[i >> 5], i & 31);
            a0 = fmaf(zi, W1[i * P_DIM + lane], a0);
            if (lane < 18) a1 = fmaf(zi, W1[i * P_DIM + 32 + lane], a1);
        }
        float p10 = fmaxf(a0, 0.f), p11 = fmaxf(a1, 0.f);

        // layer 2
        float c0 = b2[lane];
        float c1 = (lane < 18) ? b2[32 + lane] : 0.f;
        for (int i = 0; i < P_DIM; i++) {
            float pi = __shfl_sync(0xffffffffu, (i < 32) ? p10 : p11, i & 31);
            c0 = fmaf(pi, W2[i * P_DIM + lane], c0);
            if (lane < 18) c1 = fmaf(pi, W2[i * P_DIM + 32 + lane], c1);
        }
        float p20 = fmaxf(c0, 0.f), p21 = fmaxf(c1, 0.f);

        // xk = p2 @ K1 + lstm_b ; j = lane + 32q, q=0..12
        float acc[13];
        #pragma unroll
        for (int q = 0; q < 13; q++) {
            int j = lane + 32 * q;
            acc[q] = (j < G4) ? lstm_b[j] : 0.f;
        }
        for (int i = 0; i < P_DIM; i++) {
            float pi = __shfl_sync(0xffffffffu, (i < 32) ? p20 : p21, i & 31);
            const float* kr = lstm_k + (size_t)i * G4;
            #pragma unroll
            for (int q = 0; q < 13; q++) {
                int j = lane + 32 * q;
                if (j < G4) acc[q] = fmaf(pi, kr[j], acc[q]);
            }
        }
        float* xo = g_xk + (size_t)b * G4;
        #pragma unroll
        for (int q = 0; q < 13; q++) {
            int j = lane + 32 * q;
            if (j < G4) xo[j] = acc[q];
        }
    }
}

// ---------------------------------------------------------------------------
// Kernel B: 40-step rollout. One CTA = 64 batch elements, lstm_r in SMEM,
// c in registers, h through SMEM. Thread tile: 4 elems x 5 units x 4 gates.
// ---------------------------------------------------------------------------
__global__ void __launch_bounds__(NTHR, 1) rollout_kernel(
    const float* __restrict__ idm_params, // B x 5
    const float* __restrict__ idm_s,      // B x T x 12
    const float* __restrict__ sdv_acts,   // B x T x 2
    const float* __restrict__ lstm_k,     // 52 x 400 (rows 50,51 used)
    const float* __restrict__ lstm_r,     // 100 x 400
    const float* __restrict__ att_w,      // 100
    const float* __restrict__ att_b,      // 1
    float* __restrict__ out)              // [acts(B*T), atts(B*T)]
{
    extern __shared__ float sm[];
    float* R_sh    = sm;              // 100*400        [k*400 + j]
    float* K2_sh   = sm + 40000;      // 2*400
    float* aw_sh   = sm + 40800;      // 100
    float* h_sh    = sm + 40960;      // 100*HS         [k*HS + m]
    float* sdv_sh  = sm + 40960 + 100 * HS;        // 2*64
    float* part_sh = sm + 40960 + 100 * HS + 128;  // 64*20  [m*20 + ug]

    const int tid = threadIdx.x;
    // cooperative weight loads
    for (int i = tid; i < H_DIM * G4; i += NTHR) R_sh[i] = lstm_r[i];
    for (int i = tid; i < 2 * G4;     i += NTHR) K2_sh[i] = lstm_k[50 * G4 + i];
    for (int i = tid; i < H_DIM;      i += NTHR) aw_sh[i] = att_w[i];
    for (int i = tid; i < H_DIM * HS; i += NTHR) h_sh[i] = 0.f;
    const float attb = att_b[0];

    const int mg = tid / 20;          // 0..15
    const int ug = tid % 20;          // 0..19
    const int m0 = mg * 4;            // local element base
    const int b0 = blockIdx.x * MCH;  // global batch base

    float c_reg[4][5];
    #pragma unroll
    for (int mm = 0; mm < 4; mm++)
        #pragma unroll
        for (int q = 0; q < 5; q++) c_reg[mm][q] = 0.f;

    // designated-thread (ug==0) persistent state
    float ego_v[4], ego_x[4], vdes[4], tgap[4], jamx[4], amax[4], gden[4];
    if (ug == 0) {
        #pragma unroll
        for (int mm = 0; mm < 4; mm++) {
            int b = b0 + m0 + mm;
            const float* s0 = idm_s + (size_t)b * T_STEPS * 12;
            ego_v[mm] = s0[0];
            ego_x[mm] = s0[3];
            vdes[mm] = idm_params[b * 5 + 0];
            tgap[mm] = idm_params[b * 5 + 1];
            jamx[mm] = idm_params[b * 5 + 2];
            amax[mm] = idm_params[b * 5 + 3];
            float amin = idm_params[b * 5 + 4];
            gden[mm] = 2.f * sqrtf(amax[mm] * amin);
        }
    }
    __syncthreads();  // weights + h zeros ready

    for (int t = 0; t < T_STEPS; t++) {
        // phase 0: stage sdv for this step
        if (ug == 0) {
            #pragma unroll
            for (int mm = 0; mm < 4; mm++) {
                int b = b0 + m0 + mm;
                const float* sd = sdv_acts + ((size_t)b * T_STEPS + t) * 2;
                sdv_sh[m0 + mm]      = sd[0];
                sdv_sh[64 + m0 + mm] = sd[1];
            }
        }
        __syncthreads();  // S1: sdv ready, prev h final

        // phase 1: z = xk + sdv@K2 + h@R
        float acc[4][5][4];
        #pragma unroll
        for (int mm = 0; mm < 4; mm++) {
            const float* xk = g_xk + (size_t)(b0 + m0 + mm) * G4;
            float s0 = sdv_sh[m0 + mm];
            float s1 = sdv_sh[64 + m0 + mm];
            #pragma unroll
            for (int q = 0; q < 5; q++) {
                #pragma unroll
                for (int g = 0; g < 4; g++) {
                    int j = ug + 20 * q + 100 * g;
                    acc[mm][q][g] = xk[j] + s0 * K2_sh[j] + s1 * K2_sh[G4 + j];
                }
            }
        }
        if (t > 0) {  // h==0 at t==0
            #pragma unroll 2
            for (int k = 0; k < H_DIM; k++) {
                float4 hv4 = *reinterpret_cast<const float4*>(&h_sh[k * HS + m0]);
                float hvv[4] = {hv4.x, hv4.y, hv4.z, hv4.w};
                const float* Rk = R_sh + k * G4;
                #pragma unroll
                for (int q = 0; q < 5; q++) {
                    #pragma unroll
                    for (int g = 0; g < 4; g++) {
                        float r = Rk[ug + 20 * q + 100 * g];
                        #pragma unroll
                        for (int mm = 0; mm < 4; mm++)
                            acc[mm][q][g] = fmaf(hvv[mm], r, acc[mm][q][g]);
                    }
                }
            }
        }
        __syncthreads();  // S2: everyone done reading old h_sh

        // phase 2: gates, new c/h, att partials
        float att_part[4] = {0.f, 0.f, 0.f, 0.f};
        #pragma unroll
        for (int mm = 0; mm < 4; mm++) {
            #pragma unroll
            for (int q = 0; q < 5; q++) {
                int u = ug + 20 * q;
                float ig = 1.f / (1.f + expf(-acc[mm][q][0]));
                float fg = 1.f / (1.f + expf(-acc[mm][q][1]));
                float gg = tanhf(acc[mm][q][2]);
                float og = 1.f / (1.f + expf(-acc[mm][q][3]));
                float c  = fg * c_reg[mm][q] + ig * gg;
                c_reg[mm][q] = c;
                float h = tanhf(c) * og;
                h_sh[u * HS + m0 + mm] = h;
                att_part[mm] = fmaf(h, aw_sh[u], att_part[mm]);
            }
        }
        #pragma unroll
        for (int mm = 0; mm < 4; mm++) part_sh[(m0 + mm) * 20 + ug] = att_part[mm];
        __syncthreads();  // S3: h_sh & partials ready

        // phase 3: designated thread — att, IDM, integrate, store
        if (ug == 0) {
            #pragma unroll
            for (int mm = 0; mm < 4; mm++) {
                int b = b0 + m0 + mm;
                const float* srow = idm_s + ((size_t)b * T_STEPS + t) * 12;
                float fv  = srow[1],  mv  = srow[2];
                float fx  = srow[4],  mx  = srow[5];
                float fex = srow[10], mex = srow[11];

                float s = 0.f;
                #pragma unroll
                for (int p = 0; p < 20; p++) s += part_sh[(m0 + mm) * 20 + p];
                float att = 1.f / (1.f + expf(-(s + attb)));
                att = (fex * att + (1.f - fex)) * mex;

                float v = ego_v[mm], x = ego_x[mm];
                // IDM front
                float dx1 = fminf(fmaxf(fx - x, 0.1f), 1000.f);
                float dv1 = v - fv;
                float gap1 = tgap[mm] * v + v * dv1 / gden[mm];
                float dg1  = jamx[mm] + fmaxf(gap1, 0.f);
                float r1   = v / vdes[mm];  float r1s = r1 * r1;
                float r2   = dg1 / dx1;
                float ef   = amax[mm] * (1.f - r1s * r1s - r2 * r2);
                ef = fminf(fmaxf(ef, -100000.f), 100000.f);
                // IDM merge
                float dx2 = fminf(fmaxf(mx - x, 0.1f), 1000.f);
                float dv2 = v - mv;
                float gap2 = tgap[mm] * v + v * dv2 / gden[mm];
                float dg2  = jamx[mm] + fmaxf(gap2, 0.f);
                float r3   = dg2 / dx2;
                float em   = amax[mm] * (1.f - r1s * r1s - r3 * r3);
                em = fminf(fmaxf(em, -100000.f), 100000.f);

                float act = (1.f - att) * ef + att * em;
                float vn  = v + act * DT;
                ego_x[mm] = x + vn * DT + 0.5f * act * DT * DT;
                ego_v[mm] = vn;

                out[(size_t)b * T_STEPS + t] = act;
                out[(size_t)B_TOT * T_STEPS + (size_t)b * T_STEPS + t] = att;
            }
        }
    }
}

// ---------------------------------------------------------------------------
extern "C" void kernel_launch(void* const* d_in, const int* in_sizes, int n_in,
                              void* d_out, int out_size) {
    const float* sampled_z  = (const float*)d_in[0];
    const float* idm_params = (const float*)d_in[1];
    const float* idm_s      = (const float*)d_in[2];
    const float* sdv_acts   = (const float*)d_in[3];
    const float* W1         = (const float*)d_in[4];
    const float* b1         = (const float*)d_in[5];
    const float* W2         = (const float*)d_in[6];
    const float* b2         = (const float*)d_in[7];
    const float* lstm_k     = (const float*)d_in[8];
    const float* lstm_r     = (const float*)d_in[9];
    const float* lstm_b     = (const float*)d_in[10];
    const float* att_w      = (const float*)d_in[11];
    const float* att_b      = (const float*)d_in[12];
    float* out = (float*)d_out;

    const int smem_bytes = (40960 + 100 * HS + 128 + 64 * 20) * sizeof(float);
    cudaFuncSetAttribute(rollout_kernel,
                         cudaFuncAttributeMaxDynamicSharedMemorySize, smem_bytes);

    proj_xk_kernel<<<1024, 256>>>(sampled_z, W1, b1, W2, b2, lstm_k, lstm_b);
    rollout_kernel<<<B_TOT / MCH, NTHR, smem_bytes>>>(
        idm_params, idm_s, sdv_acts, lstm_k, lstm_r, att_w, att_b, out);
}

// round 3
// speedup vs baseline: 2.5435x; 2.5435x over previous
#include <cuda_runtime.h>
#include <cuda_bf16.h>

#define B_TOT   65536
#define TST     40
#define G4      400
#define DT      0.1f
#define MCH     64       // batch rows per CTA
#define NTHR    256
#define NPAD    416      // padded N (52 tiles of 8)
#define KPAD    128      // padded K elems per row (256 B)

// ---- SMEM layout (byte offsets) ----
#define OFF_R    0               // 416*256 = 106496
#define OFF_H0   106496          // 64*256 = 16384
#define OFF_H1   122880          // 16384
#define OFF_Z    139264          // 208*66*4 = 54912
#define OFF_ATT  194176          // 4*64*4 = 1024
#define OFF_AW   195200          // 104*4 = 416
#define SMEM_BYTES 195616

// ---- static device scratch ----
__device__ float                       g_xk[(size_t)B_TOT * G4];   // permuted col=4u+g
__device__ __align__(16) __nv_bfloat16 g_Rimg[NPAD * KPAD];        // pre-swizzled B image

// ============================ helpers ============================
__device__ __forceinline__ unsigned smem_u32(const void* p) {
    unsigned a;
    asm("{ .reg .u64 t; cvta.to.shared.u64 t, %1; cvt.u32.u64 %0, t; }" : "=r"(a) : "l"(p));
    return a;
}
__device__ __forceinline__ float fast_ex2(float x){ float y; asm("ex2.approx.f32 %0,%1;" : "=f"(y) : "f"(x)); return y; }
__device__ __forceinline__ float fast_rcp(float x){ float y; asm("rcp.approx.f32 %0,%1;" : "=f"(y) : "f"(x)); return y; }
__device__ __forceinline__ float fsigm(float x){ return fast_rcp(1.f + fast_ex2(-1.4426950408889634f * x)); }
__device__ __forceinline__ float htanh(float x){ float y; asm("tanh.approx.f32 %0,%1;" : "=f"(y) : "f"(x)); return y; }

// swizzled byte offset within an operand image: row-major [row][k], 256B rows,
// 16B chunks XOR'd by (row&7) for conflict-free ldmatrix
__host__ __device__ __forceinline__ unsigned sw_off(int row, int k) {
    return (unsigned)row * 256u
         + (((((unsigned)k >> 3) ^ ((unsigned)row & 7u)) << 4) | (((unsigned)k & 7u) * 2u));
}

__device__ __forceinline__ void ldsm_x4(unsigned* r, unsigned addr) {
    asm volatile("ldmatrix.sync.aligned.m8n8.x4.shared.b16 {%0,%1,%2,%3}, [%4];"
        : "=r"(r[0]), "=r"(r[1]), "=r"(r[2]), "=r"(r[3]) : "r"(addr));
}
__device__ __forceinline__ void ldsm_x2(unsigned& r0, unsigned& r1, unsigned addr) {
    asm volatile("ldmatrix.sync.aligned.m8n8.x2.shared.b16 {%0,%1}, [%2];"
        : "=r"(r0), "=r"(r1) : "r"(addr));
}
__device__ __forceinline__ void mma_bf16(float* c, const unsigned* a, unsigned b0, unsigned b1) {
    asm volatile("mma.sync.aligned.m16n8k16.row.col.f32.bf16.bf16.f32 "
        "{%0,%1,%2,%3}, {%4,%5,%6,%7}, {%8,%9}, {%0,%1,%2,%3};"
        : "+f"(c[0]), "+f"(c[1]), "+f"(c[2]), "+f"(c[3])
        : "r"(a[0]), "r"(a[1]), "r"(a[2]), "r"(a[3]), "r"(b0), "r"(b1));
}

// ============================ prep: R image (+K2 rows) ============================
__global__ void __launch_bounds__(256) prep_kernel(const float* __restrict__ lstm_k,
                                                   const float* __restrict__ lstm_r) {
    int i = blockIdx.x * blockDim.x + threadIdx.x;
    if (i >= NPAD * KPAD) return;
    int n = i / KPAD, k = i % KPAD;
    float v = 0.f;
    if (n < 400) {
        int u = n >> 2, g = n & 3, col = u + 100 * g;
        if (k < 100)       v = lstm_r[(size_t)k * G4 + col];
        else if (k == 100) v = lstm_k[(size_t)50 * G4 + col];
        else if (k == 101) v = lstm_k[(size_t)51 * G4 + col];
    }
    g_Rimg[sw_off(n, k) >> 1] = __float2bfloat16_rn(v);
}

// ============================ proj + xk (permuted 4u+g) ============================
__global__ void __launch_bounds__(256) proj_xk_kernel(
    const float* __restrict__ z, const float* __restrict__ W1, const float* __restrict__ b1,
    const float* __restrict__ W2, const float* __restrict__ b2,
    const float* __restrict__ lstm_k, const float* __restrict__ lstm_b)
{
    const int warp = threadIdx.x >> 5, lane = threadIdx.x & 31, wpc = blockDim.x >> 5;
    for (int b = blockIdx.x * wpc + warp; b < B_TOT; b += gridDim.x * wpc) {
        float zr[4];
        #pragma unroll
        for (int q = 0; q < 4; q++) zr[q] = z[(size_t)b * 128 + q * 32 + lane];

        float a0 = b1[lane];
        float a1 = (lane < 18) ? b1[32 + lane] : 0.f;
        for (int i = 0; i < 128; i++) {
            float zi = __shfl_sync(0xffffffffu, zr[i >> 5], i & 31);
            a0 = fmaf(zi, W1[i * 50 + lane], a0);
            if (lane < 18) a1 = fmaf(zi, W1[i * 50 + 32 + lane], a1);
        }
        float p10 = fmaxf(a0, 0.f), p11 = fmaxf(a1, 0.f);

        float c0 = b2[lane];
        float c1 = (lane < 18) ? b2[32 + lane] : 0.f;
        for (int i = 0; i < 50; i++) {
            float pi = __shfl_sync(0xffffffffu, (i < 32) ? p10 : p11, i & 31);
            c0 = fmaf(pi, W2[i * 50 + lane], c0);
            if (lane < 18) c1 = fmaf(pi, W2[i * 50 + 32 + lane], c1);
        }
        float p20 = fmaxf(c0, 0.f), p21 = fmaxf(c1, 0.f);

        float acc[13];
        #pragma unroll
        for (int q = 0; q < 13; q++) { int j = lane + 32 * q; acc[q] = (j < G4) ? lstm_b[j] : 0.f; }
        for (int i = 0; i < 50; i++) {
            float pi = __shfl_sync(0xffffffffu, (i < 32) ? p20 : p21, i & 31);
            const float* kr = lstm_k + (size_t)i * G4;
            #pragma unroll
            for (int q = 0; q < 13; q++) { int j = lane + 32 * q; if (j < G4) acc[q] = fmaf(pi, kr[j], acc[q]); }
        }
        float* xo = g_xk + (size_t)b * G4;
        #pragma unroll
        for (int q = 0; q < 13; q++) {
            int j = lane + 32 * q;
            if (j < G4) xo[4 * (j % 100) + (j / 100)] = acc[q];
        }
    }
}

// ============================ rollout ============================
__global__ void __launch_bounds__(NTHR, 1) rollout_kernel(
    const float* __restrict__ idm_params, const float* __restrict__ idm_s,
    const float* __restrict__ sdv_acts,   const float* __restrict__ att_w,
    const float* __restrict__ att_b,      float* __restrict__ out)
{
    extern __shared__ char sm[];
    const unsigned sbase = smem_u32(sm);
    float* z_f   = (float*)(sm + OFF_Z);
    float* att_f = (float*)(sm + OFF_ATT);
    float* aw_f  = (float*)(sm + OFF_AW);

    const int tid = threadIdx.x, lane = tid & 31, wid = tid >> 5;

    // ---- init: R image copy, zero h bufs, att_w ----
    {
        const uint4* src = (const uint4*)g_Rimg;
        uint4* dR = (uint4*)(sm + OFF_R);
        for (int i = tid; i < 106496 / 16; i += NTHR) dR[i] = src[i];
        uint4 zz = make_uint4(0, 0, 0, 0);
        uint4* dH = (uint4*)(sm + OFF_H0);
        for (int i = tid; i < 32768 / 16; i += NTHR) dH[i] = zz;
        for (int i = tid; i < 104; i += NTHR) aw_f[i] = (i < 100) ? att_w[i] : 0.f;
    }

    // ---- GEMM role ----
    const int mt = wid & 3;                 // m-tile (16 rows)
    const int ns = wid >> 2;                // n-subtile within phase (104 cols)
    const int cg = lane >> 2, ct = lane & 3;

    const int amat = lane >> 3, alr = lane & 7;
    const int arow = 16 * mt + alr + ((amat & 1) << 3);
    const int akoff = amat >> 1;
    const int bl = lane & 15, blr = bl & 7, bko = bl >> 3;

    // ---- epilogue / IDM role ----
    const int em = tid & 63, eq = tid >> 6;
    const int b_ep = blockIdx.x * MCH + em;
    const int r0m = em % 13;
    const float* xkrow = g_xk + (size_t)b_ep * G4;

    float c_st[26];
    #pragma unroll
    for (int i = 0; i < 26; i++) c_st[i] = 0.f;

    float ego_v = 0.f, ego_x = 0.f, vdes = 1.f, tgap = 0.f, jamx = 0.f, amax = 0.f, gden = 1.f, attb = 0.f;
    if (tid < MCH) {
        const int b = blockIdx.x * MCH + tid;
        const float* s0p = idm_s + (size_t)b * TST * 12;
        ego_v = s0p[0]; ego_x = s0p[3];
        vdes = idm_params[b * 5 + 0]; tgap = idm_params[b * 5 + 1];
        jamx = idm_params[b * 5 + 2]; amax = idm_params[b * 5 + 3];
        gden = 2.f * sqrtf(amax * idm_params[b * 5 + 4]);
        attb = att_b[0];
    }
    __syncthreads();

    for (int t = 0; t < TST; t++) {
        const unsigned hcur_off = (t & 1) ? OFF_H1 : OFF_H0;
        const unsigned hnxt_off = (t & 1) ? OFF_H0 : OFF_H1;

        // stage sdv(t) into A image rows at k=100,101
        if (tid < MCH) {
            const int b = blockIdx.x * MCH + tid;
            const float2 sd = *(const float2*)(sdv_acts + ((size_t)b * TST + t) * 2);
            __nv_bfloat162 pk = __floats2bfloat162_rn(sd.x, sd.y);
            *(unsigned*)(sm + hcur_off + sw_off(tid, 100)) = *(unsigned*)&pk;
        }
        __syncthreads();

        // hoist A fragments for this step
        unsigned afr[7][4];
        #pragma unroll
        for (int s = 0; s < 7; s++) {
            unsigned addr = sbase + hcur_off + (unsigned)arow * 256u
                          + ((unsigned)(((2 * s + akoff) ^ (arow & 7)) << 4));
            ldsm_x4(afr[s], addr);
        }

        float attp = 0.f;

        #pragma unroll
        for (int p = 0; p < 2; p++) {
            // ---- GEMM phase p: cols [p*208, p*208+208) ----
            float C[13][4];
            #pragma unroll
            for (int nt = 0; nt < 13; nt++)
                #pragma unroll
                for (int q = 0; q < 4; q++) C[nt][q] = 0.f;

            #pragma unroll
            for (int s = 0; s < 7; s++) {
                #pragma unroll
                for (int nt = 0; nt < 13; nt++) {
                    const int n = p * 208 + ns * 104 + nt * 8 + blr;
                    unsigned baddr = sbase + OFF_R + (unsigned)n * 256u
                                   + ((unsigned)(((2 * s + bko) ^ (n & 7)) << 4));
                    unsigned b0, b1;
                    ldsm_x2(b0, b1, baddr);
                    mma_bf16(C[nt], afr[s], b0, b1);
                }
            }
            // store z (local col j, stride 66 floats)
            #pragma unroll
            for (int nt = 0; nt < 13; nt++) {
                const int j = ns * 104 + nt * 8 + 2 * ct;
                const int mr = 16 * mt + cg;
                z_f[j * 66 + mr]           = C[nt][0];
                z_f[(j + 1) * 66 + mr]     = C[nt][1];
                z_f[j * 66 + mr + 8]       = C[nt][2];
                z_f[(j + 1) * 66 + mr + 8] = C[nt][3];
            }
            __syncthreads();

            // ---- epilogue phase p ----
            #pragma unroll
            for (int i = 0; i < 13; i++) {
                int rot = r0m + i; if (rot >= 13) rot -= 13;
                const int ul = eq * 13 + rot;
                const int u  = p * 52 + ul;
                if (u < 100) {
                    const float4 xv = *(const float4*)(xkrow + 4 * u);
                    const int j0 = 4 * ul;
                    float z0 = z_f[j0 * 66 + em]       + xv.x;
                    float z1 = z_f[(j0 + 1) * 66 + em] + xv.y;
                    float z2 = z_f[(j0 + 2) * 66 + em] + xv.z;
                    float z3 = z_f[(j0 + 3) * 66 + em] + xv.w;
                    float ig = fsigm(z0), fg = fsigm(z1);
                    float gg = htanh(z2), og = fsigm(z3);
                    float cn = fg * c_st[p * 13 + i] + ig * gg;
                    c_st[p * 13 + i] = cn;
                    float h = htanh(cn) * og;
                    attp = fmaf(h, aw_f[u], attp);
                    *(__nv_bfloat16*)(sm + hnxt_off + sw_off(em, u)) = __float2bfloat16_rn(h);
                }
            }
            if (p == 1) att_f[eq * 64 + em] = attp;
            __syncthreads();
        }

        // ---- att mix + IDM + integrate + store (threads 0..63) ----
        if (tid < MCH) {
            const int b = blockIdx.x * MCH + tid;
            const float* srow = idm_s + ((size_t)b * TST + t) * 12;
            float fv = srow[1], mv = srow[2], fx = srow[4], mx = srow[5];
            float fex = srow[10], mex = srow[11];

            float att = fsigm(att_f[tid] + att_f[64 + tid] + att_f[128 + tid] + att_f[192 + tid] + attb);
            att = (fex * att + (1.f - fex)) * mex;

            float v = ego_v, x = ego_x;
            float dx1 = fminf(fmaxf(fx - x, 0.1f), 1000.f);
            float gap1 = tgap * v + v * (v - fv) / gden;
            float dg1 = jamx + fmaxf(gap1, 0.f);
            float r1 = v / vdes; float r1s = r1 * r1;
            float r2 = dg1 / dx1;
            float ef = amax * (1.f - r1s * r1s - r2 * r2);
            ef = fminf(fmaxf(ef, -100000.f), 100000.f);

            float dx2 = fminf(fmaxf(mx - x, 0.1f), 1000.f);
            float gap2 = tgap * v + v * (v - mv) / gden;
            float dg2 = jamx + fmaxf(gap2, 0.f);
            float r3 = dg2 / dx2;
            float em2 = amax * (1.f - r1s * r1s - r3 * r3);
            em2 = fminf(fmaxf(em2, -100000.f), 100000.f);

            float act = (1.f - att) * ef + att * em2;
            float vn = v + act * DT;
            ego_x = x + vn * DT + 0.5f * act * DT * DT;
            ego_v = vn;

            out[(size_t)b * TST + t] = act;
            out[(size_t)B_TOT * TST + (size_t)b * TST + t] = att;
        }
    }
}

// ============================ launch ============================
extern "C" void kernel_launch(void* const* d_in, const int* in_sizes, int n_in,
                              void* d_out, int out_size) {
    const float* sampled_z  = (const float*)d_in[0];
    const float* idm_params = (const float*)d_in[1];
    const float* idm_s      = (const float*)d_in[2];
    const float* sdv_acts   = (const float*)d_in[3];
    const float* W1         = (const float*)d_in[4];
    const float* b1         = (const float*)d_in[5];
    const float* W2         = (const float*)d_in[6];
    const float* b2         = (const float*)d_in[7];
    const float* lstm_k     = (const float*)d_in[8];
    const float* lstm_r     = (const float*)d_in[9];
    const float* lstm_b     = (const float*)d_in[10];
    const float* att_w      = (const float*)d_in[11];
    const float* att_b      = (const float*)d_in[12];
    float* out = (float*)d_out;

    cudaFuncSetAttribute(rollout_kernel, cudaFuncAttributeMaxDynamicSharedMemorySize, SMEM_BYTES);

    prep_kernel<<<(NPAD * KPAD + 255) / 256, 256>>>(lstm_k, lstm_r);
    proj_xk_kernel<<<1024, 256>>>(sampled_z, W1, b1, W2, b2, lstm_k, lstm_b);
    rollout_kernel<<<B_TOT / MCH, NTHR, SMEM_BYTES>>>(idm_params, idm_s, sdv_acts, att_w, att_b, out);
}

// round 4
// speedup vs baseline: 2.8871x; 1.1351x over previous
#include <cuda_runtime.h>
#include <cuda_bf16.h>

#define B_TOT   65536
#define TST     40
#define G4      400
#define DT      0.1f
#define MCH     64        // batch rows per CTA
#define NTHR    384       // 8 GEMM warps + 4 EPI warps
#define NPAD    416       // padded N
#define KPAD    160       // padded K elems (153 used), 320B rows
#define ROWB    320
#define ZS      65        // z buffer row stride (floats)

// ---- SMEM byte offsets ----
#define OFF_R    0                 // 416*320 = 133120
#define OFF_A0   133120            // 64*320  = 20480
#define OFF_A1   153600            // 20480
#define OFF_Z    174080            // 208*65*4 = 54080
#define OFF_ATT  228160            // 2*64*4 = 512
#define OFF_AW   228672            // 100*4 = 400
#define SMEM_BYTES 229072

// ---- static device scratch ----
__device__ __align__(16) __nv_bfloat16 g_proj[(size_t)B_TOT * 50];
__device__ __align__(16) __nv_bfloat16 g_Rimg[NPAD * KPAD];

// ============================ helpers ============================
__device__ __forceinline__ unsigned smem_u32(const void* p) {
    unsigned a;
    asm("{ .reg .u64 t; cvta.to.shared.u64 t, %1; cvt.u32.u64 %0, t; }" : "=r"(a) : "l"(p));
    return a;
}
__device__ __forceinline__ float fast_ex2(float x){ float y; asm("ex2.approx.f32 %0,%1;" : "=f"(y) : "f"(x)); return y; }
__device__ __forceinline__ float fast_rcp(float x){ float y; asm("rcp.approx.f32 %0,%1;" : "=f"(y) : "f"(x)); return y; }
__device__ __forceinline__ float fsigm(float x){ return fast_rcp(1.f + fast_ex2(-1.4426950408889634f * x)); }
__device__ __forceinline__ float htanh(float x){ float y; asm("tanh.approx.f32 %0,%1;" : "=f"(y) : "f"(x)); return y; }
__device__ __forceinline__ float tsigm(float x){ return fmaf(0.5f, htanh(0.5f * x), 0.5f); }

// physical byte offset inside an operand image (320B rows, split swizzle:
// chunks 0..15 XOR row&7; chunks 16..19 XOR row&3 within the group)
__host__ __device__ __forceinline__ unsigned phys_off(int row, int k) {
    unsigned c = (unsigned)k >> 3;
    unsigned pc = (c < 16u) ? (c ^ ((unsigned)row & 7u))
                            : (16u + ((c & 3u) ^ ((unsigned)row & 3u)));
    return (unsigned)row * ROWB + (pc << 4) + (((unsigned)k & 7u) * 2u);
}
__device__ __forceinline__ unsigned phys_chunk_off(int row, int c) {
    unsigned pc = ((unsigned)c < 16u) ? ((unsigned)c ^ ((unsigned)row & 7u))
                                      : (16u + (((unsigned)c & 3u) ^ ((unsigned)row & 3u)));
    return (unsigned)row * ROWB + (pc << 4);
}

__device__ __forceinline__ void ldsm_x4(unsigned* r, unsigned addr) {
    asm volatile("ldmatrix.sync.aligned.m8n8.x4.shared.b16 {%0,%1,%2,%3}, [%4];"
        : "=r"(r[0]), "=r"(r[1]), "=r"(r[2]), "=r"(r[3]) : "r"(addr));
}
__device__ __forceinline__ void mma_bf16(float* c, const unsigned* a, unsigned b0, unsigned b1) {
    asm volatile("mma.sync.aligned.m16n8k16.row.col.f32.bf16.bf16.f32 "
        "{%0,%1,%2,%3}, {%4,%5,%6,%7}, {%8,%9}, {%0,%1,%2,%3};"
        : "+f"(c[0]), "+f"(c[1]), "+f"(c[2]), "+f"(c[3])
        : "r"(a[0]), "r"(a[1]), "r"(a[2]), "r"(a[3]), "r"(b0), "r"(b1));
}
#define BAR_ARRIVE(id, cnt) asm volatile("bar.arrive %0, %1;" :: "r"(id), "r"(cnt) : "memory")
#define BAR_SYNC(id, cnt)   asm volatile("bar.sync %0, %1;"   :: "r"(id), "r"(cnt) : "memory")

// ============================ prep: B image ============================
// B[n][k]: n=4u+g, col=u+100g.  k<100: R[k][col]; 100/101: K2 rows; 102..151:
// K1[k-102][col]; 152: lstm_b[col]; else 0.
__global__ void __launch_bounds__(256) prep_kernel(const float* __restrict__ lstm_k,
                                                   const float* __restrict__ lstm_r,
                                                   const float* __restrict__ lstm_b) {
    int i = blockIdx.x * blockDim.x + threadIdx.x;
    if (i >= NPAD * KPAD) return;
    int n = i / KPAD, k = i % KPAD;
    float v = 0.f;
    if (n < 400) {
        int u = n >> 2, g = n & 3, col = u + 100 * g;
        if (k < 100)        v = lstm_r[(size_t)k * G4 + col];
        else if (k < 102)   v = lstm_k[(size_t)(50 + (k - 100)) * G4 + col];
        else if (k < 152)   v = lstm_k[(size_t)(k - 102) * G4 + col];
        else if (k == 152)  v = lstm_b[col];
    }
    g_Rimg[phys_off(n, k) >> 1] = __float2bfloat16_rn(v);
}

// ============================ proj kernel ============================
__global__ void __launch_bounds__(256) proj_kernel(
    const float* __restrict__ z, const float* __restrict__ W1, const float* __restrict__ b1,
    const float* __restrict__ W2, const float* __restrict__ b2)
{
    const int warp = threadIdx.x >> 5, lane = threadIdx.x & 31, wpc = blockDim.x >> 5;
    for (int b = blockIdx.x * wpc + warp; b < B_TOT; b += gridDim.x * wpc) {
        float zr[4];
        #pragma unroll
        for (int q = 0; q < 4; q++) zr[q] = z[(size_t)b * 128 + q * 32 + lane];

        float a0 = b1[lane];
        float a1 = (lane < 18) ? b1[32 + lane] : 0.f;
        for (int i = 0; i < 128; i++) {
            float zi = __shfl_sync(0xffffffffu, zr[i >> 5], i & 31);
            a0 = fmaf(zi, W1[i * 50 + lane], a0);
            if (lane < 18) a1 = fmaf(zi, W1[i * 50 + 32 + lane], a1);
        }
        float p10 = fmaxf(a0, 0.f), p11 = fmaxf(a1, 0.f);

        float c0 = b2[lane];
        float c1 = (lane < 18) ? b2[32 + lane] : 0.f;
        for (int i = 0; i < 50; i++) {
            float pi = __shfl_sync(0xffffffffu, (i < 32) ? p10 : p11, i & 31);
            c0 = fmaf(pi, W2[i * 50 + lane], c0);
            if (lane < 18) c1 = fmaf(pi, W2[i * 50 + 32 + lane], c1);
        }
        g_proj[(size_t)b * 50 + lane] = __float2bfloat16_rn(fmaxf(c0, 0.f));
        if (lane < 18)
            g_proj[(size_t)b * 50 + 32 + lane] = __float2bfloat16_rn(fmaxf(c1, 0.f));
    }
}

// ============================ rollout ============================
__global__ void __launch_bounds__(NTHR, 1) rollout_kernel(
    const float* __restrict__ idm_params, const float* __restrict__ idm_s,
    const float* __restrict__ sdv_acts,   const float* __restrict__ att_w,
    const float* __restrict__ att_b,      float* __restrict__ out)
{
    extern __shared__ char sm[];
    const unsigned sbase = smem_u32(sm);
    float* zf    = (float*)(sm + OFF_Z);
    float* att_f = (float*)(sm + OFF_ATT);
    float* aw_f  = (float*)(sm + OFF_AW);

    const int tid = threadIdx.x, lane = tid & 31, wid = tid >> 5;
    const int b0 = blockIdx.x * MCH;

    // ---- init ----
    {
        const uint4* src = (const uint4*)g_Rimg;
        uint4* dR = (uint4*)(sm + OFF_R);
        for (int i = tid; i < 133120 / 16; i += NTHR) dR[i] = src[i];
        uint4 zz = make_uint4(0, 0, 0, 0);
        uint4* dA = (uint4*)(sm + OFF_A0);
        for (int i = tid; i < 40960 / 16; i += NTHR) dA[i] = zz;
        for (int i = tid; i < 100; i += NTHR) aw_f[i] = att_w[i];
    }
    __syncthreads();
    // proj (k=102..151) + bias (k=152) into BOTH A buffers; sdv(0) into A0
    for (int idx = tid; idx < MCH * 51; idx += NTHR) {
        int row = idx / 51, jj = idx % 51;
        __nv_bfloat16 v = (jj < 50) ? g_proj[(size_t)(b0 + row) * 50 + jj]
                                    : __float2bfloat16_rn(1.0f);
        unsigned off = phys_off(row, 102 + jj);
        *(__nv_bfloat16*)(sm + OFF_A0 + off) = v;
        *(__nv_bfloat16*)(sm + OFF_A1 + off) = v;
    }
    if (tid < MCH) {
        const float2 sd = *(const float2*)(sdv_acts + (size_t)(b0 + tid) * TST * 2);
        __nv_bfloat162 pk = __floats2bfloat162_rn(sd.x, sd.y);
        *(unsigned*)(sm + OFF_A0 + phys_off(tid, 100)) = *(unsigned*)&pk;
    }

    // ---- roles ----
    const bool is_gemm = tid < 256;
    // GEMM role
    const int mt = wid & 3, ns = (wid >> 2) & 1;
    const int amat = lane >> 3;
    const int arow = 16 * mt + (lane & 7) + ((amat & 1) << 3);
    const int akoff = amat >> 1;
    const int cg = lane >> 2, ct = lane & 3;
    const int bnr = lane & 7, bq = lane >> 3;
    // EPI role
    const int et = tid - 256;
    const int erow = et & 63, ehalf = (et >> 6) & 1;
    const int eb = b0 + erow;

    float c_st[52];
    #pragma unroll
    for (int i = 0; i < 52; i++) c_st[i] = 0.f;

    float ego_v = 0.f, ego_x = 0.f, vdes = 1.f, tgap = 0.f, jamx = 0.f,
          amax = 0.f, gden = 1.f, attb = 0.f;
    if (!is_gemm && et < MCH) {
        const float* s0p = idm_s + (size_t)eb * TST * 12;
        ego_v = s0p[0]; ego_x = s0p[3];
        vdes = idm_params[eb * 5 + 0]; tgap = idm_params[eb * 5 + 1];
        jamx = idm_params[eb * 5 + 2]; amax = idm_params[eb * 5 + 3];
        gden = 2.f * sqrtf(amax * idm_params[eb * 5 + 4]);
        attb = att_b[0];
    }
    __syncthreads();

    for (int t = 0; t < TST; t++) {
        const unsigned acur = (t & 1) ? OFF_A1 : OFF_A0;
        const unsigned anxt = (t & 1) ? OFF_A0 : OFF_A1;

        if (is_gemm) {
            // ---- A fragments for this step ----
            unsigned afr[10][4];
            #pragma unroll
            for (int s = 0; s < 10; s++)
                ldsm_x4(afr[s], sbase + acur + phys_chunk_off(arow, 2 * s + akoff));

            float C[13][4];
            #pragma unroll
            for (int p = 0; p < 2; p++) {
                #pragma unroll
                for (int nt = 0; nt < 13; nt++)
                    #pragma unroll
                    for (int q = 0; q < 4; q++) C[nt][q] = 0.f;
                const int nb = p * 208 + ns * 104;
                #pragma unroll
                for (int s2 = 0; s2 < 5; s2++) {
                    #pragma unroll
                    for (int nt = 0; nt < 13; nt++) {
                        const int n = nb + nt * 8 + bnr;
                        unsigned b4[4];
                        ldsm_x4(b4, sbase + OFF_R + phys_chunk_off(n, 4 * s2 + bq));
                        mma_bf16(C[nt], afr[2 * s2],     b4[0], b4[1]);
                        mma_bf16(C[nt], afr[2 * s2 + 1], b4[2], b4[3]);
                    }
                }
                if (p == 1) BAR_SYNC(2, 384);   // epi done reading z(p0)
                #pragma unroll
                for (int nt = 0; nt < 13; nt++) {
                    const int j = ns * 104 + nt * 8 + 2 * ct;
                    const int mr = 16 * mt + cg;
                    zf[j * ZS + mr]           = C[nt][0];
                    zf[(j + 1) * ZS + mr]     = C[nt][1];
                    zf[j * ZS + mr + 8]       = C[nt][2];
                    zf[(j + 1) * ZS + mr + 8] = C[nt][3];
                }
                BAR_ARRIVE(p == 0 ? 1 : 3, 384);
            }
        } else {
            float attp = 0.f;
            #pragma unroll
            for (int p = 0; p < 2; p++) {
                BAR_SYNC(p == 0 ? 1 : 3, 384);
                const int u0  = p * 52 + ehalf * 26;
                const int cnt = (p == 1 && ehalf == 1) ? 22 : 26;
                #pragma unroll
                for (int ii = 0; ii < 26; ii += 2) {
                    if (ii < cnt) {
                        const int ul = ehalf * 26 + ii;
                        float h2[2];
                        #pragma unroll
                        for (int w = 0; w < 2; w++) {
                            const int jb = (4 * (ul + w)) * ZS + erow;
                            float z0 = zf[jb], z1 = zf[jb + ZS];
                            float z2 = zf[jb + 2 * ZS], z3 = zf[jb + 3 * ZS];
                            float ig = tsigm(z0);
                            float fg = fsigm(z1);
                            float gg = htanh(z2);
                            float og = tsigm(z3);
                            float cn = fg * c_st[p * 26 + ii + w] + ig * gg;
                            c_st[p * 26 + ii + w] = cn;
                            h2[w] = htanh(cn) * og;
                            attp = fmaf(h2[w], aw_f[u0 + ii + w], attp);
                        }
                        __nv_bfloat162 pk = __floats2bfloat162_rn(h2[0], h2[1]);
                        *(unsigned*)(sm + anxt + phys_off(erow, u0 + ii)) = *(unsigned*)&pk;
                    }
                }
                if (p == 0) BAR_ARRIVE(2, 384);
            }
            att_f[ehalf * 64 + erow] = attp;
            BAR_SYNC(4, 128);

            if (et < MCH) {
                const float* srow = idm_s + ((size_t)eb * TST + t) * 12;
                float fv = srow[1], mv = srow[2], fx = srow[4], mx = srow[5];
                float fex = srow[10], mex = srow[11];

                float att = fsigm(att_f[erow] + att_f[64 + erow] + attb);
                att = (fex * att + (1.f - fex)) * mex;

                float v = ego_v, x = ego_x;
                float dx1 = fminf(fmaxf(fx - x, 0.1f), 1000.f);
                float gap1 = tgap * v + v * (v - fv) / gden;
                float dg1 = jamx + fmaxf(gap1, 0.f);
                float r1 = v / vdes; float r1s = r1 * r1;
                float r2 = dg1 / dx1;
                float ef = amax * (1.f - r1s * r1s - r2 * r2);
                ef = fminf(fmaxf(ef, -100000.f), 100000.f);

                float dx2 = fminf(fmaxf(mx - x, 0.1f), 1000.f);
                float gap2 = tgap * v + v * (v - mv) / gden;
                float dg2 = jamx + fmaxf(gap2, 0.f);
                float r3 = dg2 / dx2;
                float em2 = amax * (1.f - r1s * r1s - r3 * r3);
                em2 = fminf(fmaxf(em2, -100000.f), 100000.f);

                float act = (1.f - att) * ef + att * em2;
                float vn = v + act * DT;
                ego_x = x + vn * DT + 0.5f * act * DT * DT;
                ego_v = vn;

                out[(size_t)eb * TST + t] = act;
                out[(size_t)B_TOT * TST + (size_t)eb * TST + t] = att;

                if (t + 1 < TST) {   // stage sdv(t+1) into the buffer epi is filling
                    const float2 sd = *(const float2*)(sdv_acts + ((size_t)eb * TST + t + 1) * 2);
                    __nv_bfloat162 pk = __floats2bfloat162_rn(sd.x, sd.y);
                    *(unsigned*)(sm + anxt + phys_off(erow, 100)) = *(unsigned*)&pk;
                }
            }
        }
        __syncthreads();
    }
}

// ============================ launch ============================
extern "C" void kernel_launch(void* const* d_in, const int* in_sizes, int n_in,
                              void* d_out, int out_size) {
    const float* sampled_z  = (const float*)d_in[0];
    const float* idm_params = (const float*)d_in[1];
    const float* idm_s      = (const float*)d_in[2];
    const float* sdv_acts   = (const float*)d_in[3];
    const float* W1         = (const float*)d_in[4];
    const float* b1         = (const float*)d_in[5];
    const float* W2         = (const float*)d_in[6];
    const float* b2         = (const float*)d_in[7];
    const float* lstm_k     = (const float*)d_in[8];
    const float* lstm_r     = (const float*)d_in[9];
    const float* lstm_b     = (const float*)d_in[10];
    const float* att_w      = (const float*)d_in[11];
    const float* att_b      = (const float*)d_in[12];
    float* out = (float*)d_out;

    cudaFuncSetAttribute(rollout_kernel, cudaFuncAttributeMaxDynamicSharedMemorySize, SMEM_BYTES);

    prep_kernel<<<(NPAD * KPAD + 255) / 256, 256>>>(lstm_k, lstm_r, lstm_b);
    proj_kernel<<<1024, 256>>>(sampled_z, W1, b1, W2, b2);
    rollout_kernel<<<B_TOT / MCH, NTHR, SMEM_BYTES>>>(idm_params, idm_s, sdv_acts, att_w, att_b, out);
}